// round 2
// baseline (speedup 1.0000x reference)
#include <cuda_runtime.h>
#include <cstdint>

#define NN      100000
#define HID     256
#define KDIM    256
#define NSLOTS  800

// ---------------- scratch (allocation-free: __device__ globals) ----------------
__device__ __align__(128) float g_z  [(size_t)NN * HID];  // GEMM output (z1, then z2)
__device__ __align__(128) float g_h  [(size_t)NN * HID];  // tanh(agg1)
__device__ __align__(128) float g_agg[(size_t)NN * HID];  // scatter accumulator
__device__ __align__(128) float g_sums[NSLOTS * HID];
__device__ __align__(128) float g_cnt [NSLOTS];

// ---------------- helpers ----------------
__device__ __forceinline__ void ffma2(float2& c, const float2& a, const float2& b) {
    // packed fp32 FMA: c.x += a.x*b.x ; c.y += a.y*b.y   (2x FFMA throughput on sm_103a)
    asm("fma.rn.f32x2 %0, %1, %2, %0;"
        : "+l"(*reinterpret_cast<unsigned long long*>(&c))
        : "l"(*reinterpret_cast<const unsigned long long*>(&a)),
          "l"(*reinterpret_cast<const unsigned long long*>(&b)));
}

__device__ __forceinline__ void red_add_v4(float4* p, const float4 v) {
    asm volatile("red.global.add.v4.f32 [%0], {%1, %2, %3, %4};"
                 :: "l"(p), "f"(v.x), "f"(v.y), "f"(v.z), "f"(v.w)
                 : "memory");
}

// ---------------- zero kernels ----------------
__global__ void zero_agg_kernel() {
    const size_t total4 = (size_t)NN * HID / 4;
    float4* p = reinterpret_cast<float4*>(g_agg);
    float4 z = make_float4(0.f, 0.f, 0.f, 0.f);
    for (size_t i = (size_t)blockIdx.x * blockDim.x + threadIdx.x; i < total4;
         i += (size_t)gridDim.x * blockDim.x)
        p[i] = z;
}

__global__ void zero_pool_kernel() {
    int i = blockIdx.x * blockDim.x + threadIdx.x;
    if (i < NSLOTS * HID) g_sums[i] = 0.f;
    if (i < NSLOTS)       g_cnt[i]  = 0.f;
}

// ---------------- GEMM: C(g_z) = A @ W + bias ----------------
// M x 256 x 256, BM=128 BN=64 BK=32, 256 threads, thread tile 8x4,
// accumulation in float2 pairs along K via fma.rn.f32x2.
#define BM 128
#define BN 64
#define BK 32

__global__ __launch_bounds__(256, 2)
void gemm_kernel(const float* __restrict__ A_in, const float* __restrict__ W,
                 const float* __restrict__ bias, int M, int useGH) {
    __shared__ float As[BM][BK + 2];   // [m][k], stride 34 (8B-aligned rows)
    __shared__ float Bs[BN][BK + 2];   // [n][k]

    const float* __restrict__ A = useGH ? g_h : A_in;

    const int tid = threadIdx.x;
    const int tx = tid & 15;          // n group (4 cols each)
    const int ty = tid >> 4;          // m group (8 rows each)
    const int m_base = blockIdx.y * BM;
    const int n_base = blockIdx.x * BN;

    float2 acc[8][4];
#pragma unroll
    for (int i = 0; i < 8; i++)
#pragma unroll
        for (int j = 0; j < 4; j++) acc[i][j] = make_float2(0.f, 0.f);

    for (int k0 = 0; k0 < KDIM; k0 += BK) {
        // A tile: 128x32 = 1024 float4-loads... actually 1024 float4? 128*32/4=1024. 4 per thread.
#pragma unroll
        for (int l = 0; l < 4; l++) {
            int idx = tid + l * 256;          // 0..1023
            int r   = idx >> 3;               // row in tile
            int c4  = (idx & 7) << 2;         // col (float4 granule)
            int gm  = m_base + r;
            float4 v = make_float4(0.f, 0.f, 0.f, 0.f);
            if (gm < M)
                v = *reinterpret_cast<const float4*>(A + (size_t)gm * KDIM + k0 + c4);
            As[r][c4 + 0] = v.x; As[r][c4 + 1] = v.y;
            As[r][c4 + 2] = v.z; As[r][c4 + 3] = v.w;
        }
        // B tile: W[k0..k0+31][n_base..n_base+63] -> Bs[n][k] (transposed store)
#pragma unroll
        for (int l = 0; l < 2; l++) {
            int idx = tid + l * 256;          // 0..511
            int kr  = idx >> 4;               // k row
            int c4  = (idx & 15) << 2;        // n (float4 granule)
            float4 v = *reinterpret_cast<const float4*>(
                W + (size_t)(k0 + kr) * KDIM + n_base + c4);
            Bs[c4 + 0][kr] = v.x; Bs[c4 + 1][kr] = v.y;
            Bs[c4 + 2][kr] = v.z; Bs[c4 + 3][kr] = v.w;
        }
        __syncthreads();

#pragma unroll
        for (int kk = 0; kk < BK / 2; kk++) {
            float2 a_frag[8], b_frag[4];
#pragma unroll
            for (int i = 0; i < 8; i++)
                a_frag[i] = *reinterpret_cast<const float2*>(&As[ty * 8 + i][kk * 2]);
#pragma unroll
            for (int j = 0; j < 4; j++)
                b_frag[j] = *reinterpret_cast<const float2*>(&Bs[tx * 4 + j][kk * 2]);
#pragma unroll
            for (int i = 0; i < 8; i++)
#pragma unroll
                for (int j = 0; j < 4; j++)
                    ffma2(acc[i][j], a_frag[i], b_frag[j]);
        }
        __syncthreads();
    }

#pragma unroll
    for (int i = 0; i < 8; i++) {
        int gm = m_base + ty * 8 + i;
        if (gm < M) {
#pragma unroll
            for (int j = 0; j < 4; j++) {
                int gn = n_base + tx * 4 + j;
                g_z[(size_t)gm * HID + gn] = acc[i][j].x + acc[i][j].y + bias[gn];
            }
        }
    }
}

// ---------------- edge scatter: g_agg[dst] += g_z[src], one warp per edge ----------------
__global__ void scatter_kernel(const int* __restrict__ esrc,
                               const int* __restrict__ edst, int E) {
    int gw   = (blockIdx.x * blockDim.x + threadIdx.x) >> 5;
    int lane = threadIdx.x & 31;
    if (gw >= E) return;
    int s = __ldg(esrc + gw);
    int d = __ldg(edst + gw);
    const float4* zs = reinterpret_cast<const float4*>(g_z + (size_t)s * HID);
    float4*       ad = reinterpret_cast<float4*>(g_agg + (size_t)d * HID);
    float4 v0 = __ldg(zs + lane);
    float4 v1 = __ldg(zs + lane + 32);
    red_add_v4(ad + lane,      v0);
    red_add_v4(ad + lane + 32, v1);
}

// ---------------- h = tanh(agg); agg = 0 (fused re-zero) ----------------
__global__ void tanh_zero_kernel() {
    const size_t total4 = (size_t)NN * HID / 4;
    float4* pa = reinterpret_cast<float4*>(g_agg);
    float4* ph = reinterpret_cast<float4*>(g_h);
    float4 z = make_float4(0.f, 0.f, 0.f, 0.f);
    for (size_t i = (size_t)blockIdx.x * blockDim.x + threadIdx.x; i < total4;
         i += (size_t)gridDim.x * blockDim.x) {
        float4 v = pa[i];
        v.x = tanhf(v.x); v.y = tanhf(v.y); v.z = tanhf(v.z); v.w = tanhf(v.w);
        ph[i] = v;
        pa[i] = z;
    }
}

// ---------------- pooling: sums[seg[n]] += tanh(agg2[n]); cnt[seg[n]] += 1 ----------------
__global__ void pool_kernel(const int* __restrict__ seg, int n_nodes) {
    int gw   = (blockIdx.x * blockDim.x + threadIdx.x) >> 5;
    int lane = threadIdx.x & 31;
    if (gw >= n_nodes) return;
    int s = __ldg(seg + gw);
    const float4* a  = reinterpret_cast<const float4*>(g_agg + (size_t)gw * HID);
    float4*       dp = reinterpret_cast<float4*>(g_sums + (size_t)s * HID);
    float4 v0 = a[lane];
    float4 v1 = a[lane + 32];
    v0.x = tanhf(v0.x); v0.y = tanhf(v0.y); v0.z = tanhf(v0.z); v0.w = tanhf(v0.w);
    v1.x = tanhf(v1.x); v1.y = tanhf(v1.y); v1.z = tanhf(v1.z); v1.w = tanhf(v1.w);
    red_add_v4(dp + lane,      v0);
    red_add_v4(dp + lane + 32, v1);
    if (lane == 0) atomicAdd(&g_cnt[s], 1.0f);
}

// ---------------- finalize: out = sums / max(cnt, 1) ----------------
__global__ void finalize_kernel(float* __restrict__ out) {
    int i = blockIdx.x * blockDim.x + threadIdx.x;
    if (i < NSLOTS * HID) {
        float c = g_cnt[i >> 8];
        out[i] = g_sums[i] / fmaxf(c, 1.0f);
    }
}

// ---------------- launch ----------------
extern "C" void kernel_launch(void* const* d_in, const int* in_sizes, int n_in,
                              void* d_out, int out_size) {
    const float* h    = (const float*)d_in[0];
    const float* W1   = (const float*)d_in[1];
    const float* b1   = (const float*)d_in[2];
    const float* W2   = (const float*)d_in[3];
    const float* b2   = (const float*)d_in[4];
    const int*   esrc = (const int*)d_in[5];
    const int*   edst = (const int*)d_in[6];
    const int*   seg  = (const int*)d_in[7];
    float*       out  = (float*)d_out;

    const int M = in_sizes[0] / HID;   // 100000
    const int E = in_sizes[5];         // 1600000

    dim3 gemm_grid((HID + BN - 1) / BN, (M + BM - 1) / BM);   // (4, 782)
    int  scatter_blocks = (E + 7) / 8;                        // warp per edge, 8 warps/block
    int  pool_blocks    = (M + 7) / 8;

    zero_agg_kernel<<<4736, 256>>>();
    zero_pool_kernel<<<(NSLOTS * HID + 255) / 256, 256>>>();

    // layer 1
    gemm_kernel<<<gemm_grid, 256>>>(h, W1, b1, M, 0);
    scatter_kernel<<<scatter_blocks, 256>>>(esrc, edst, E);
    tanh_zero_kernel<<<4736, 256>>>();            // g_h = tanh(agg1); agg = 0

    // layer 2
    gemm_kernel<<<gemm_grid, 256>>>(h, W2, b2, M, 1);   // reads g_h
    scatter_kernel<<<scatter_blocks, 256>>>(esrc, edst, E);

    // pooling (tanh fused) + finalize
    pool_kernel<<<pool_blocks, 256>>>(seg, M);
    finalize_kernel<<<(NSLOTS * HID + 255) / 256, 256>>>(out);
}

// round 3
// speedup vs baseline: 1.6045x; 1.6045x over previous
#include <cuda_runtime.h>
#include <cstdint>

#define NN      100000
#define NE      1600000
#define HID     256
#define KDIM    256
#define NSLOTS  800
#define SCAN_BLK 1024                      // elements per scan block
#define NSCAN   ((NN + SCAN_BLK - 1) / SCAN_BLK)   // 98

// ---------------- scratch (allocation-free: __device__ globals) ----------------
__device__ __align__(128) float g_z  [(size_t)NN * HID];   // GEMM output (z1, then z2)
__device__ __align__(128) float g_h  [(size_t)NN * HID];   // tanh(agg1)
__device__ __align__(128) float g_sums[NSLOTS * HID];
__device__ float g_cnt [NSLOTS];
__device__ int   g_deg [NN];
__device__ int   g_off [NN];
__device__ int   g_cursor[NN];
__device__ int   g_part[NSCAN];
__device__ int   g_csr [NE];               // src node per edge, sorted by dst

// ---------------- helpers ----------------
__device__ __forceinline__ void ffma2(float2& c, const float2& a, const float2& b) {
    asm("fma.rn.f32x2 %0, %1, %2, %0;"
        : "+l"(*reinterpret_cast<unsigned long long*>(&c))
        : "l"(*reinterpret_cast<const unsigned long long*>(&a)),
          "l"(*reinterpret_cast<const unsigned long long*>(&b)));
}

__device__ __forceinline__ void red_add_v4(float4* p, const float4 v) {
    asm volatile("red.global.add.v4.f32 [%0], {%1, %2, %3, %4};"
                 :: "l"(p), "f"(v.x), "f"(v.y), "f"(v.z), "f"(v.w)
                 : "memory");
}

__device__ __forceinline__ float4 tanh4(float4 v) {
    v.x = tanhf(v.x); v.y = tanhf(v.y); v.z = tanhf(v.z); v.w = tanhf(v.w);
    return v;
}

// ---------------- zero: deg, sums, cnt ----------------
__global__ void zero_misc_kernel() {
    int i = blockIdx.x * blockDim.x + threadIdx.x;
    if (i < NN)            g_deg[i]  = 0;
    if (i < NSLOTS * HID)  g_sums[i] = 0.f;
    if (i < NSLOTS)        g_cnt[i]  = 0.f;
}

// ---------------- CSR build ----------------
__global__ void hist_kernel(const int* __restrict__ edst) {
    int e = blockIdx.x * blockDim.x + threadIdx.x;
    if (e < NE) atomicAdd(&g_deg[edst[e]], 1);
}

// per-block sums of g_deg (1024 elems / block)
__global__ void scan1_kernel() {
    __shared__ int sh[256];
    int tid = threadIdx.x;
    int base = blockIdx.x * SCAN_BLK + tid * 4;
    int s = 0;
    if (base < NN) {                       // NN % 4 == 0 -> full int4 safe
        int4 v = *reinterpret_cast<const int4*>(g_deg + base);
        s = v.x + v.y + v.z + v.w;
    }
    sh[tid] = s; __syncthreads();
    for (int o = 128; o > 0; o >>= 1) {
        if (tid < o) sh[tid] += sh[tid + o];
        __syncthreads();
    }
    if (tid == 0) g_part[blockIdx.x] = sh[0];
}

// serial exclusive scan of the 98 partials
__global__ void scan2_kernel() {
    if (threadIdx.x == 0) {
        int acc = 0;
        for (int i = 0; i < NSCAN; i++) {
            int v = g_part[i];
            g_part[i] = acc;
            acc += v;
        }
    }
}

// per-block exclusive scan, writes g_off and g_cursor
__global__ void scan3_kernel() {
    __shared__ int sh[256];
    int tid = threadIdx.x;
    int base = blockIdx.x * SCAN_BLK + tid * 4;
    int4 v = make_int4(0, 0, 0, 0);
    if (base < NN) v = *reinterpret_cast<const int4*>(g_deg + base);
    int t = v.x + v.y + v.z + v.w;
    sh[tid] = t; __syncthreads();
    // Hillis-Steele inclusive scan over thread totals
    for (int o = 1; o < 256; o <<= 1) {
        int add = (tid >= o) ? sh[tid - o] : 0;
        __syncthreads();
        sh[tid] += add;
        __syncthreads();
    }
    int excl = sh[tid] - t + g_part[blockIdx.x];
    if (base < NN) {
        int4 o;
        o.x = excl;
        o.y = o.x + v.x;
        o.z = o.y + v.y;
        o.w = o.z + v.z;
        *reinterpret_cast<int4*>(g_off + base)    = o;
        *reinterpret_cast<int4*>(g_cursor + base) = o;
    }
}

__global__ void fill_kernel(const int* __restrict__ esrc,
                            const int* __restrict__ edst) {
    int e = blockIdx.x * blockDim.x + threadIdx.x;
    if (e >= NE) return;
    int d   = edst[e];
    int pos = atomicAdd(&g_cursor[d], 1);
    g_csr[pos] = esrc[e];
}

// ---------------- GEMM: g_z = A @ W + bias ----------------
#define BM 128
#define BN 64
#define BK 32

__global__ __launch_bounds__(256, 2)
void gemm_kernel(const float* __restrict__ A_in, const float* __restrict__ W,
                 const float* __restrict__ bias, int M, int useGH) {
    __shared__ float As[BM][BK + 2];
    __shared__ float Bs[BN][BK + 2];

    const float* __restrict__ A = useGH ? g_h : A_in;

    const int tid = threadIdx.x;
    const int tx = tid & 15;
    const int ty = tid >> 4;
    const int m_base = blockIdx.y * BM;
    const int n_base = blockIdx.x * BN;

    float2 acc[8][4];
#pragma unroll
    for (int i = 0; i < 8; i++)
#pragma unroll
        for (int j = 0; j < 4; j++) acc[i][j] = make_float2(0.f, 0.f);

    for (int k0 = 0; k0 < KDIM; k0 += BK) {
#pragma unroll
        for (int l = 0; l < 4; l++) {
            int idx = tid + l * 256;
            int r   = idx >> 3;
            int c4  = (idx & 7) << 2;
            int gm  = m_base + r;
            float4 v = make_float4(0.f, 0.f, 0.f, 0.f);
            if (gm < M)
                v = *reinterpret_cast<const float4*>(A + (size_t)gm * KDIM + k0 + c4);
            As[r][c4 + 0] = v.x; As[r][c4 + 1] = v.y;
            As[r][c4 + 2] = v.z; As[r][c4 + 3] = v.w;
        }
#pragma unroll
        for (int l = 0; l < 2; l++) {
            int idx = tid + l * 256;
            int kr  = idx >> 4;
            int c4  = (idx & 15) << 2;
            float4 v = *reinterpret_cast<const float4*>(
                W + (size_t)(k0 + kr) * KDIM + n_base + c4);
            Bs[c4 + 0][kr] = v.x; Bs[c4 + 1][kr] = v.y;
            Bs[c4 + 2][kr] = v.z; Bs[c4 + 3][kr] = v.w;
        }
        __syncthreads();

#pragma unroll
        for (int kk = 0; kk < BK / 2; kk++) {
            float2 a_frag[8], b_frag[4];
#pragma unroll
            for (int i = 0; i < 8; i++)
                a_frag[i] = *reinterpret_cast<const float2*>(&As[ty * 8 + i][kk * 2]);
#pragma unroll
            for (int j = 0; j < 4; j++)
                b_frag[j] = *reinterpret_cast<const float2*>(&Bs[tx * 4 + j][kk * 2]);
#pragma unroll
            for (int i = 0; i < 8; i++)
#pragma unroll
                for (int j = 0; j < 4; j++)
                    ffma2(acc[i][j], a_frag[i], b_frag[j]);
        }
        __syncthreads();
    }

#pragma unroll
    for (int i = 0; i < 8; i++) {
        int gm = m_base + ty * 8 + i;
        if (gm < M) {
#pragma unroll
            for (int j = 0; j < 4; j++) {
                int gn = n_base + tx * 4 + j;
                g_z[(size_t)gm * HID + gn] = acc[i][j].x + acc[i][j].y + bias[gn];
            }
        }
    }
}

// ---------------- gather-aggregate (CSR), warp per dst node ----------------
// acc = sum_{s in csr[node]} z[s]; then tanh. Layer1: write g_h. Layer2: pool.
__device__ __forceinline__ void gather_node(int node, int lane,
                                            float4& a0, float4& a1) {
    int start = g_off[node];
    int d     = g_deg[node];
    const float4* Z = reinterpret_cast<const float4*>(g_z);
    a0 = make_float4(0.f, 0.f, 0.f, 0.f);
    a1 = make_float4(0.f, 0.f, 0.f, 0.f);
    int i = 0;
    for (; i + 2 <= d; i += 2) {
        int s0 = __ldg(&g_csr[start + i]);
        int s1 = __ldg(&g_csr[start + i + 1]);
        float4 v00 = __ldg(Z + (size_t)s0 * 64 + lane);
        float4 v01 = __ldg(Z + (size_t)s0 * 64 + lane + 32);
        float4 v10 = __ldg(Z + (size_t)s1 * 64 + lane);
        float4 v11 = __ldg(Z + (size_t)s1 * 64 + lane + 32);
        a0.x += v00.x; a0.y += v00.y; a0.z += v00.z; a0.w += v00.w;
        a1.x += v01.x; a1.y += v01.y; a1.z += v01.z; a1.w += v01.w;
        a0.x += v10.x; a0.y += v10.y; a0.z += v10.z; a0.w += v10.w;
        a1.x += v11.x; a1.y += v11.y; a1.z += v11.z; a1.w += v11.w;
    }
    if (i < d) {
        int s0 = __ldg(&g_csr[start + i]);
        float4 v00 = __ldg(Z + (size_t)s0 * 64 + lane);
        float4 v01 = __ldg(Z + (size_t)s0 * 64 + lane + 32);
        a0.x += v00.x; a0.y += v00.y; a0.z += v00.z; a0.w += v00.w;
        a1.x += v01.x; a1.y += v01.y; a1.z += v01.z; a1.w += v01.w;
    }
}

__global__ void agg1_kernel() {
    int node = (blockIdx.x * blockDim.x + threadIdx.x) >> 5;
    int lane = threadIdx.x & 31;
    if (node >= NN) return;
    float4 a0, a1;
    gather_node(node, lane, a0, a1);
    float4* H = reinterpret_cast<float4*>(g_h) + (size_t)node * 64;
    H[lane]      = tanh4(a0);
    H[lane + 32] = tanh4(a1);
}

__global__ void agg2_pool_kernel(const int* __restrict__ seg) {
    int node = (blockIdx.x * blockDim.x + threadIdx.x) >> 5;
    int lane = threadIdx.x & 31;
    if (node >= NN) return;
    float4 a0, a1;
    gather_node(node, lane, a0, a1);
    int s = __ldg(seg + node);
    float4* dp = reinterpret_cast<float4*>(g_sums) + (size_t)s * 64;
    red_add_v4(dp + lane,      tanh4(a0));
    red_add_v4(dp + lane + 32, tanh4(a1));
    if (lane == 0) atomicAdd(&g_cnt[s], 1.0f);
}

// ---------------- finalize: out = sums / max(cnt, 1) ----------------
__global__ void finalize_kernel(float* __restrict__ out) {
    int i = blockIdx.x * blockDim.x + threadIdx.x;
    if (i < NSLOTS * HID) {
        float c = g_cnt[i >> 8];
        out[i] = g_sums[i] / fmaxf(c, 1.0f);
    }
}

// ---------------- launch ----------------
extern "C" void kernel_launch(void* const* d_in, const int* in_sizes, int n_in,
                              void* d_out, int out_size) {
    const float* h    = (const float*)d_in[0];
    const float* W1   = (const float*)d_in[1];
    const float* b1   = (const float*)d_in[2];
    const float* W2   = (const float*)d_in[3];
    const float* b2   = (const float*)d_in[4];
    const int*   esrc = (const int*)d_in[5];
    const int*   edst = (const int*)d_in[6];
    const int*   seg  = (const int*)d_in[7];
    float*       out  = (float*)d_out;

    const int M = in_sizes[0] / HID;   // 100000
    const int E = in_sizes[5];         // 1600000
    (void)E;

    dim3 gemm_grid((HID + BN - 1) / BN, (M + BM - 1) / BM);
    int  agg_blocks = (M * 32 + 255) / 256;            // warp per node
    int  edge_blocks = (NE + 255) / 256;

    // CSR build (dst-sorted gather lists)
    zero_misc_kernel<<<(NSLOTS * HID + 255) / 256, 256>>>();
    hist_kernel<<<edge_blocks, 256>>>(edst);
    scan1_kernel<<<NSCAN, 256>>>();
    scan2_kernel<<<1, 32>>>();
    scan3_kernel<<<NSCAN, 256>>>();
    fill_kernel<<<edge_blocks, 256>>>(esrc, edst);

    // layer 1
    gemm_kernel<<<gemm_grid, 256>>>(h, W1, b1, M, 0);
    agg1_kernel<<<agg_blocks, 256>>>();                 // g_h = tanh(gather(z))

    // layer 2
    gemm_kernel<<<gemm_grid, 256>>>(h, W2, b2, M, 1);   // reads g_h
    agg2_pool_kernel<<<agg_blocks, 256>>>(seg);         // fused tanh + pooling

    finalize_kernel<<<(NSLOTS * HID + 255) / 256, 256>>>(out);
}

// round 5
// speedup vs baseline: 3.0328x; 1.8901x over previous
#include <cuda_runtime.h>
#include <cstdint>

#define NN      100000
#define NE      1600000
#define HID     256
#define KDIM    256
#define NSLOTS  800
#define SCAN_BLK 1024
#define NSCAN   ((NN + SCAN_BLK - 1) / SCAN_BLK)   // 98

// ---------------- scratch ----------------
__device__ __align__(128) float g_z  [(size_t)NN * HID];
__device__ __align__(128) float g_h  [(size_t)NN * HID];
__device__ __align__(128) float g_sums[NSLOTS * HID];
__device__ float g_cnt [NSLOTS];
__device__ int   g_deg [NN];
__device__ int   g_off [NN];
__device__ int   g_cursor[NN];
__device__ int   g_part[NSCAN];
__device__ int   g_csr [NE];

// ---------------- helpers ----------------
__device__ __forceinline__ void red_add_v4(float4* p, const float4 v) {
    asm volatile("red.global.add.v4.f32 [%0], {%1, %2, %3, %4};"
                 :: "l"(p), "f"(v.x), "f"(v.y), "f"(v.z), "f"(v.w)
                 : "memory");
}
__device__ __forceinline__ float4 tanh4(float4 v) {
    v.x = tanhf(v.x); v.y = tanhf(v.y); v.z = tanhf(v.z); v.w = tanhf(v.w);
    return v;
}
__device__ __forceinline__ uint32_t f2tf32(float f) {
    uint32_t r;
    asm("cvt.rna.tf32.f32 %0, %1;" : "=r"(r) : "f"(f));
    return r;
}

// ---------------- zero / CSR build ----------------
__global__ void zero_misc_kernel() {
    int i = blockIdx.x * blockDim.x + threadIdx.x;
    if (i < NN)            g_deg[i]  = 0;
    if (i < NSLOTS * HID)  g_sums[i] = 0.f;
    if (i < NSLOTS)        g_cnt[i]  = 0.f;
}
__global__ void hist_kernel(const int* __restrict__ edst) {
    int e = blockIdx.x * blockDim.x + threadIdx.x;
    if (e < NE) atomicAdd(&g_deg[edst[e]], 1);
}
__global__ void scan1_kernel() {
    __shared__ int sh[256];
    int tid = threadIdx.x;
    int base = blockIdx.x * SCAN_BLK + tid * 4;
    int s = 0;
    if (base < NN) {
        int4 v = *reinterpret_cast<const int4*>(g_deg + base);
        s = v.x + v.y + v.z + v.w;
    }
    sh[tid] = s; __syncthreads();
    for (int o = 128; o > 0; o >>= 1) {
        if (tid < o) sh[tid] += sh[tid + o];
        __syncthreads();
    }
    if (tid == 0) g_part[blockIdx.x] = sh[0];
}
__global__ void scan2_kernel() {
    if (threadIdx.x == 0) {
        int acc = 0;
        for (int i = 0; i < NSCAN; i++) { int v = g_part[i]; g_part[i] = acc; acc += v; }
    }
}
__global__ void scan3_kernel() {
    __shared__ int sh[256];
    int tid = threadIdx.x;
    int base = blockIdx.x * SCAN_BLK + tid * 4;
    int4 v = make_int4(0, 0, 0, 0);
    if (base < NN) v = *reinterpret_cast<const int4*>(g_deg + base);
    int t = v.x + v.y + v.z + v.w;
    sh[tid] = t; __syncthreads();
    for (int o = 1; o < 256; o <<= 1) {
        int add = (tid >= o) ? sh[tid - o] : 0;
        __syncthreads();
        sh[tid] += add;
        __syncthreads();
    }
    int excl = sh[tid] - t + g_part[blockIdx.x];
    if (base < NN) {
        int4 o;
        o.x = excl; o.y = o.x + v.x; o.z = o.y + v.y; o.w = o.z + v.z;
        *reinterpret_cast<int4*>(g_off + base)    = o;
        *reinterpret_cast<int4*>(g_cursor + base) = o;
    }
}
__global__ void fill_kernel(const int* __restrict__ esrc, const int* __restrict__ edst) {
    int e = blockIdx.x * blockDim.x + threadIdx.x;
    if (e >= NE) return;
    int d   = edst[e];
    int pos = atomicAdd(&g_cursor[d], 1);
    g_csr[pos] = esrc[e];
}

// ---------------- tf32 mma.sync GEMM: g_z = A @ W + bias ----------------
// CTA 128x128, K chunks of 32, double-buffered smem, 8 warps (2x4),
// warp tile 64x32 via m16n8k8 tf32 mma.sync.
#define BK      32
#define NCH     (KDIM / BK)            // 8
#define AS_STRIDE 36                   // floats per A row (bank: 4g+c, conflict-free)
#define BS_STRIDE 136                  // floats per B k-row (bank: 8r+g, conflict-free)
#define A_STG   (128 * AS_STRIDE)      // 4608 floats
#define B_STG   (BK * BS_STRIDE)       // 4352 floats
#define GEMM_SMEM_BYTES ((2 * A_STG + 2 * B_STG) * 4)   // 71680

__device__ __forceinline__ void mma_tf32(float* d, const uint32_t* a, const uint32_t* b) {
    asm volatile(
        "mma.sync.aligned.m16n8k8.row.col.f32.tf32.tf32.f32 "
        "{%0,%1,%2,%3}, {%4,%5,%6,%7}, {%8,%9}, {%0,%1,%2,%3};"
        : "+f"(d[0]), "+f"(d[1]), "+f"(d[2]), "+f"(d[3])
        : "r"(a[0]), "r"(a[1]), "r"(a[2]), "r"(a[3]), "r"(b[0]), "r"(b[1]));
}

__device__ __forceinline__ void gemm_fill(const float* __restrict__ A,
                                          const float* __restrict__ W,
                                          int m_base, int n_base, int M, int k0,
                                          float* Af, float* Bf, int tid) {
    // A: 128 rows x 32 k -> Af[r * 36 + k], tf32-converted, STS.128
#pragma unroll
    for (int l = 0; l < 4; l++) {
        int idx = tid + l * 256;          // 0..1023
        int r   = idx >> 3;
        int c4  = (idx & 7) << 2;
        int gm  = m_base + r;
        float4 v = make_float4(0.f, 0.f, 0.f, 0.f);
        if (gm < M)
            v = *reinterpret_cast<const float4*>(A + (size_t)gm * KDIM + k0 + c4);
        uint4 t;
        t.x = f2tf32(v.x); t.y = f2tf32(v.y); t.z = f2tf32(v.z); t.w = f2tf32(v.w);
        *reinterpret_cast<uint4*>(Af + r * AS_STRIDE + c4) = t;
    }
    // B: 32 k x 128 n -> Bf[k * 136 + n]
#pragma unroll
    for (int l = 0; l < 4; l++) {
        int idx = tid + l * 256;          // 0..1023
        int k   = idx >> 5;
        int n4  = (idx & 31) << 2;
        float4 v = *reinterpret_cast<const float4*>(
            W + (size_t)(k0 + k) * HID + n_base + n4);
        uint4 t;
        t.x = f2tf32(v.x); t.y = f2tf32(v.y); t.z = f2tf32(v.z); t.w = f2tf32(v.w);
        *reinterpret_cast<uint4*>(Bf + k * BS_STRIDE + n4) = t;
    }
}

__global__ __launch_bounds__(256, 2)
void gemm_mma_kernel(const float* __restrict__ A_in, const float* __restrict__ W,
                     const float* __restrict__ bias, int M, int useGH) {
    extern __shared__ float smem[];
    const float* __restrict__ A = useGH ? g_h : A_in;

    const int tid    = threadIdx.x;
    const int wid    = tid >> 5;
    const int lane   = tid & 31;
    const int warp_m = wid >> 2;         // 0..1 (64 rows each)
    const int warp_n = wid & 3;          // 0..3 (32 cols each)
    const int m_base = blockIdx.y * 128;
    const int n_base = blockIdx.x * 128;

    float* Asm[2] = { smem,             smem + A_STG };
    float* Bsm[2] = { smem + 2 * A_STG, smem + 2 * A_STG + B_STG };

    float acc[4][4][4];                  // [mt][nt][frag]
#pragma unroll
    for (int i = 0; i < 4; i++)
#pragma unroll
        for (int j = 0; j < 4; j++)
#pragma unroll
            for (int f = 0; f < 4; f++) acc[i][j][f] = 0.f;

    gemm_fill(A, W, m_base, n_base, M, 0, Asm[0], Bsm[0], tid);
    __syncthreads();

    const int g   = lane >> 2;
    const int cth = lane & 3;

    for (int c = 0; c < NCH; c++) {
        int cur = c & 1;
        const float* As = Asm[cur];
        const float* Bs = Bsm[cur];

        if (c + 1 < NCH)
            gemm_fill(A, W, m_base, n_base, M, (c + 1) * BK,
                      Asm[1 - cur], Bsm[1 - cur], tid);

#pragma unroll
        for (int ks = 0; ks < 4; ks++) {
            uint32_t afr[4][4], bfr[4][2];
#pragma unroll
            for (int mt = 0; mt < 4; mt++) {
                const float* p = As + (warp_m * 64 + mt * 16 + g) * AS_STRIDE + ks * 8 + cth;
                afr[mt][0] = __float_as_uint(p[0]);
                afr[mt][1] = __float_as_uint(p[8 * AS_STRIDE]);
                afr[mt][2] = __float_as_uint(p[4]);
                afr[mt][3] = __float_as_uint(p[8 * AS_STRIDE + 4]);
            }
#pragma unroll
            for (int nt = 0; nt < 4; nt++) {
                const float* p = Bs + (ks * 8 + cth) * BS_STRIDE + warp_n * 32 + nt * 8 + g;
                bfr[nt][0] = __float_as_uint(p[0]);
                bfr[nt][1] = __float_as_uint(p[4 * BS_STRIDE]);
            }
#pragma unroll
            for (int mt = 0; mt < 4; mt++)
#pragma unroll
                for (int nt = 0; nt < 4; nt++)
                    mma_tf32(acc[mt][nt], afr[mt], bfr[nt]);
        }
        __syncthreads();
    }

    // epilogue: c0/c1 at (row g), c2/c3 at (row g+8); cols 2*(lane&3), +1
#pragma unroll
    for (int mt = 0; mt < 4; mt++) {
        int r0 = m_base + warp_m * 64 + mt * 16 + g;
        int r1 = r0 + 8;
#pragma unroll
        for (int nt = 0; nt < 4; nt++) {
            int col = n_base + warp_n * 32 + nt * 8 + cth * 2;
            float b0 = __ldg(bias + col);
            float b1 = __ldg(bias + col + 1);
            if (r0 < M) {
                float2 o = make_float2(acc[mt][nt][0] + b0, acc[mt][nt][1] + b1);
                *reinterpret_cast<float2*>(g_z + (size_t)r0 * HID + col) = o;
            }
            if (r1 < M) {
                float2 o = make_float2(acc[mt][nt][2] + b0, acc[mt][nt][3] + b1);
                *reinterpret_cast<float2*>(g_z + (size_t)r1 * HID + col) = o;
            }
        }
    }
}

// ---------------- gather-aggregate (CSR), warp per dst node ----------------
__device__ __forceinline__ void gather_node(int node, int lane, float4& a0, float4& a1) {
    int start = g_off[node];
    int d     = g_deg[node];
    const float4* Z = reinterpret_cast<const float4*>(g_z);
    a0 = make_float4(0.f, 0.f, 0.f, 0.f);
    a1 = make_float4(0.f, 0.f, 0.f, 0.f);
    int i = 0;
    for (; i + 2 <= d; i += 2) {
        int s0 = __ldg(&g_csr[start + i]);
        int s1 = __ldg(&g_csr[start + i + 1]);
        float4 v00 = __ldg(Z + (size_t)s0 * 64 + lane);
        float4 v01 = __ldg(Z + (size_t)s0 * 64 + lane + 32);
        float4 v10 = __ldg(Z + (size_t)s1 * 64 + lane);
        float4 v11 = __ldg(Z + (size_t)s1 * 64 + lane + 32);
        a0.x += v00.x; a0.y += v00.y; a0.z += v00.z; a0.w += v00.w;
        a1.x += v01.x; a1.y += v01.y; a1.z += v01.z; a1.w += v01.w;
        a0.x += v10.x; a0.y += v10.y; a0.z += v10.z; a0.w += v10.w;
        a1.x += v11.x; a1.y += v11.y; a1.z += v11.z; a1.w += v11.w;
    }
    if (i < d) {
        int s0 = __ldg(&g_csr[start + i]);
        float4 v00 = __ldg(Z + (size_t)s0 * 64 + lane);
        float4 v01 = __ldg(Z + (size_t)s0 * 64 + lane + 32);
        a0.x += v00.x; a0.y += v00.y; a0.z += v00.z; a0.w += v00.w;
        a1.x += v01.x; a1.y += v01.y; a1.z += v01.z; a1.w += v01.w;
    }
}

__global__ void agg1_kernel() {
    int node = (blockIdx.x * blockDim.x + threadIdx.x) >> 5;
    int lane = threadIdx.x & 31;
    if (node >= NN) return;
    float4 a0, a1;
    gather_node(node, lane, a0, a1);
    float4* H = reinterpret_cast<float4*>(g_h) + (size_t)node * 64;
    __stcs(H + lane,      tanh4(a0));
    __stcs(H + lane + 32, tanh4(a1));
}

__global__ void agg2_pool_kernel(const int* __restrict__ seg) {
    int node = (blockIdx.x * blockDim.x + threadIdx.x) >> 5;
    int lane = threadIdx.x & 31;
    if (node >= NN) return;
    float4 a0, a1;
    gather_node(node, lane, a0, a1);
    int s = __ldg(seg + node);
    float4* dp = reinterpret_cast<float4*>(g_sums) + (size_t)s * 64;
    red_add_v4(dp + lane,      tanh4(a0));
    red_add_v4(dp + lane + 32, tanh4(a1));
    if (lane == 0) atomicAdd(&g_cnt[s], 1.0f);
}

__global__ void finalize_kernel(float* __restrict__ out) {
    int i = blockIdx.x * blockDim.x + threadIdx.x;
    if (i < NSLOTS * HID) {
        float c = g_cnt[i >> 8];
        out[i] = g_sums[i] / fmaxf(c, 1.0f);
    }
}

// ---------------- launch ----------------
extern "C" void kernel_launch(void* const* d_in, const int* in_sizes, int n_in,
                              void* d_out, int out_size) {
    const float* h    = (const float*)d_in[0];
    const float* W1   = (const float*)d_in[1];
    const float* b1   = (const float*)d_in[2];
    const float* W2   = (const float*)d_in[3];
    const float* b2   = (const float*)d_in[4];
    const int*   esrc = (const int*)d_in[5];
    const int*   edst = (const int*)d_in[6];
    const int*   seg  = (const int*)d_in[7];
    float*       out  = (float*)d_out;

    const int M = in_sizes[0] / HID;   // 100000
    const int E = in_sizes[5];
    (void)E;

    static int smem_set = 0;
    if (!smem_set) {
        cudaFuncSetAttribute(gemm_mma_kernel,
                             cudaFuncAttributeMaxDynamicSharedMemorySize,
                             GEMM_SMEM_BYTES);
        smem_set = 1;
    }

    dim3 gemm_grid(HID / 128, (M + 127) / 128);        // (2, 782)
    int  agg_blocks  = (M * 32 + 255) / 256;
    int  edge_blocks = (NE + 255) / 256;

    zero_misc_kernel<<<(NSLOTS * HID + 255) / 256, 256>>>();
    hist_kernel<<<edge_blocks, 256>>>(edst);
    scan1_kernel<<<NSCAN, 256>>>();
    scan2_kernel<<<1, 32>>>();
    scan3_kernel<<<NSCAN, 256>>>();
    fill_kernel<<<edge_blocks, 256>>>(esrc, edst);

    gemm_mma_kernel<<<gemm_grid, 256, GEMM_SMEM_BYTES>>>(h, W1, b1, M, 0);
    agg1_kernel<<<agg_blocks, 256>>>();

    gemm_mma_kernel<<<gemm_grid, 256, GEMM_SMEM_BYTES>>>(h, W2, b2, M, 1);
    agg2_pool_kernel<<<agg_blocks, 256>>>(seg);

    finalize_kernel<<<(NSLOTS * HID + 255) / 256, 256>>>(out);
}